// round 1
// baseline (speedup 1.0000x reference)
#include <cuda_runtime.h>
#include <stdint.h>

#define BB 8
#define HH 640
#define WW 640
#define NBOX 12
#define PP 256
#define IMG_ELEMS (HH*WW*3)      /* 1228800 */
#define PATCH_ELEMS (PP*PP*3)    /* 196608  */

struct BoxParam {
    float y0f, x0f, diagf, cc, ca, sa, top, phm1, sfac, delta;
    unsigned kn0, kn1;
    int valid, _pad;
};

__device__ BoxParam g_box[BB][NBOX];
__device__ float g_wmul[BB][3];
__device__ float g_badd[BB][3];
__device__ float g_part_img[1024];
__device__ float g_part_p1[256];
__device__ float g_offset[BB];
__device__ float g_patch[BB][PATCH_ELEMS];

// ---------------- threefry2x32 (JAX-exact) ----------------
__device__ __forceinline__ void tf2x32(unsigned k0, unsigned k1,
                                       unsigned x0, unsigned x1,
                                       unsigned &o0, unsigned &o1) {
    unsigned ks2 = k0 ^ k1 ^ 0x1BD11BDAu;
    x0 += k0; x1 += k1;
#define TF_R(r) { x0 += x1; x1 = (x1 << (r)) | (x1 >> (32 - (r))); x1 ^= x0; }
    TF_R(13) TF_R(15) TF_R(26) TF_R(6)
    x0 += k1;  x1 += ks2 + 1u;
    TF_R(17) TF_R(29) TF_R(16) TF_R(24)
    x0 += ks2; x1 += k0 + 2u;
    TF_R(13) TF_R(15) TF_R(26) TF_R(6)
    x0 += k0;  x1 += k1 + 3u;
    TF_R(17) TF_R(29) TF_R(16) TF_R(24)
    x0 += k1;  x1 += ks2 + 4u;
    TF_R(13) TF_R(15) TF_R(26) TF_R(6)
    x0 += ks2; x1 += k0 + 5u;
#undef TF_R
    o0 = x0; o1 = x1;
}

// partitionable-mode random bits: xor of the two output words, counter (0, idx)
__device__ __forceinline__ unsigned rbits32(unsigned k0, unsigned k1, unsigned idx) {
    unsigned a, b; tf2x32(k0, k1, 0u, idx, a, b); return a ^ b;
}
// partitionable (fold-like) split: subkey j = threefry(key, (0, j))
__device__ __forceinline__ void subkey(unsigned k0, unsigned k1, unsigned j,
                                       unsigned &s0, unsigned &s1) {
    tf2x32(k0, k1, 0u, j, s0, s1);
}
__device__ __forceinline__ float u01f(unsigned bits) {
    return __uint_as_float((bits >> 9) | 0x3f800000u) - 1.0f;
}

// XLA f32 ErfInv (Giles polynomial), explicit rn ops to match non-contracted HLO
__device__ __forceinline__ float erfinv_xla(float x) {
    float xx = __fmul_rn(x, x);
    float w = -log1pf(-xx);
    float p;
    if (w < 5.0f) {
        w = __fsub_rn(w, 2.5f);
        p = 2.81022636e-08f;
        p = __fadd_rn(__fmul_rn(p, w), 3.43273939e-07f);
        p = __fadd_rn(__fmul_rn(p, w), -3.5233877e-06f);
        p = __fadd_rn(__fmul_rn(p, w), -4.39150654e-06f);
        p = __fadd_rn(__fmul_rn(p, w), 0.00021858087f);
        p = __fadd_rn(__fmul_rn(p, w), -0.00125372503f);
        p = __fadd_rn(__fmul_rn(p, w), -0.00417768164f);
        p = __fadd_rn(__fmul_rn(p, w), 0.246640727f);
        p = __fadd_rn(__fmul_rn(p, w), 1.50140941f);
    } else {
        w = __fsub_rn(__fsqrt_rn(w), 3.0f);
        p = -0.000200214257f;
        p = __fadd_rn(__fmul_rn(p, w), 0.000100950558f);
        p = __fadd_rn(__fmul_rn(p, w), 0.00134934322f);
        p = __fadd_rn(__fmul_rn(p, w), -0.00367342844f);
        p = __fadd_rn(__fmul_rn(p, w), 0.00573950773f);
        p = __fadd_rn(__fmul_rn(p, w), -0.0076224613f);
        p = __fadd_rn(__fmul_rn(p, w), 0.00943887047f);
        p = __fadd_rn(__fmul_rn(p, w), 1.00167406f);
        p = __fadd_rn(__fmul_rn(p, w), 2.83297682f);
    }
    return __fmul_rn(p, x);
}

// jax.random.normal element i of a size-3 draw
__device__ __forceinline__ float normal_elem(unsigned k0, unsigned k1, int i) {
    unsigned bits = rbits32(k0, k1, (unsigned)i);
    const float lo = -0.99999994f;            // nextafterf(-1, 0)
    float span = __fsub_rn(1.0f, lo);
    float u = u01f(bits);
    float uu = fmaxf(lo, __fadd_rn(__fmul_rn(u, span), lo));
    return __fmul_rn(1.41421356237f, erfinv_xla(uu));  // rounds to f32(sqrt(2))
}

// ---------------- K1: all per-image / per-box scalars ----------------
__global__ void k_setup(const float* __restrict__ boxes,
                        const float* __restrict__ scale_p) {
    int t = threadIdx.x;
    float scale = *scale_p;
    if (t < BB) {
        unsigned i0, i1; subkey(0u, 42u, (unsigned)t, i0, i1);   // img key b
        unsigned kw0, kw1, kb0, kb1;
        subkey(i0, i1, 0u, kw0, kw1);                            // kw
        subkey(i0, i1, 1u, kb0, kb1);                            // kb
        for (int c = 0; c < 3; c++) {
            g_wmul[t][c] = __fadd_rn(0.5f, __fmul_rn(0.1f, normal_elem(kw0, kw1, c)));
            g_badd[t][c] = __fmul_rn(0.01f, normal_elem(kb0, kb1, c));
        }
    }
    if (t < BB * NBOX) {
        int b = t / NBOX, j = t % NBOX;
        unsigned i0, i1; subkey(0u, 42u, (unsigned)b, i0, i1);
        unsigned s0, s1; subkey(i0, i1, 2u, s0, s1);             // ks
        unsigned bk0, bk1; subkey(s0, s1, (unsigned)j, bk0, bk1);// box key j
        unsigned kc10,kc11,kc20,kc21,ka0,ka1,kd0,kd1,kn0,kn1;
        subkey(bk0,bk1,0u,kc10,kc11);
        subkey(bk0,bk1,1u,kc20,kc21);
        subkey(bk0,bk1,2u,ka0,ka1);
        subkey(bk0,bk1,3u,kd0,kd1);
        subkey(bk0,bk1,4u,kn0,kn1);
        float u1 = u01f(rbits32(kc10,kc11,0u));
        float u2 = u01f(rbits32(kc20,kc21,0u));
        float ua = u01f(rbits32(ka0,ka1,0u));
        float ud = u01f(rbits32(kd0,kd1,0u));

        const float* bx = boxes + (b*NBOX + j)*4;
        float ymin = bx[0], xmin = bx[1], ymax = bx[2], xmax = bx[3];
        float h = __fsub_rn(ymax, ymin);
        float w = __fsub_rn(xmax, xmin);
        float longer = fmaxf(h, w);
        float patch_size = floorf(__fmul_rn(longer, scale));
        float diag = fminf(__fmul_rn(1.41421356237f, patch_size), 640.0f);
        float jy = __fmul_rn(__fmul_rn(__fsub_rn(u1, 0.5f), 0.2f), h);
        float jx = __fmul_rn(__fmul_rn(__fsub_rn(u2, 0.5f), 0.2f), w);
        float oy = __fadd_rn(__fadd_rn(ymin, __fmul_rn(h, 0.5f)), jy);
        float ox = __fadd_rn(__fadd_rn(xmin, __fmul_rn(w, 0.5f)), jx);
        float ymin_p = fmaxf(__fsub_rn(oy, __fmul_rn(diag, 0.5f)), 0.0f);
        float xmin_p = fmaxf(__fsub_rn(ox, __fmul_rn(diag, 0.5f)), 0.0f);
        if (__fadd_rn(ymin_p, diag) > 640.0f) ymin_p = __fsub_rn(640.0f, diag);
        if (__fadd_rn(xmin_p, diag) > 640.0f) xmin_p = __fsub_rn(640.0f, diag);
        int valid = (__fmul_rn(patch_size, patch_size) > 4.0f) ? 1 : 0;
        float y0f = floorf(ymin_p), x0f = floorf(xmin_p);
        float phf = patch_size;
        float diagf = floorf(diag);
        float top = floorf(__fmul_rn(__fsub_rn(diagf, phf), 0.5f));
        float angle = __fmul_rn(__fsub_rn(__fmul_rn(ua, 2.0f), 1.0f),
                                0.34906585039886593f);   // 20 deg in rad
        float delta = __fmul_rn(__fsub_rn(__fmul_rn(ud, 2.0f), 1.0f), 0.3f);
        float ca = cosf(angle), sa = sinf(angle);
        float cc = __fmul_rn(__fsub_rn(diagf, 1.0f), 0.5f);
        float safe_ph = fmaxf(phf, 1.0f);
        float sfac = __fdiv_rn(256.0f, safe_ph);

        BoxParam bp;
        bp.y0f = y0f; bp.x0f = x0f; bp.diagf = diagf; bp.cc = cc;
        bp.ca = ca;   bp.sa = sa;   bp.top = top;
        bp.phm1 = __fsub_rn(phf, 1.0f);
        bp.sfac = sfac; bp.delta = delta;
        bp.kn0 = kn0; bp.kn1 = kn1; bp.valid = valid; bp._pad = 0;
        g_box[b][j] = bp;
    }
}

// ---------------- K2: image mean partials (deterministic) ----------------
__global__ void k_img_partial(const float* __restrict__ images) {
    __shared__ float sh[256];
    int blk = blockIdx.x;            // 0..1023, 128 per image
    int b = blk >> 7, s = blk & 127;
    const float* base = images + (size_t)b * IMG_ELEMS + s * 9600;
    float acc = 0.f;
    for (int i = threadIdx.x; i < 9600; i += 256) acc += base[i];
    sh[threadIdx.x] = acc; __syncthreads();
    for (int o = 128; o > 0; o >>= 1) {
        if (threadIdx.x < o) sh[threadIdx.x] += sh[threadIdx.x + o];
        __syncthreads();
    }
    if (threadIdx.x == 0) g_part_img[blk] = sh[0];
}

// ---------------- K3: adjusted-patch mean partials ----------------
__global__ void k_p1_partial(const float* __restrict__ patch) {
    __shared__ float sh[256];
    int blk = blockIdx.x;            // 0..255, 32 per image
    int b = blk >> 5, s = blk & 31;
    int start = s * 6144;
    float wm0 = g_wmul[b][0], wm1 = g_wmul[b][1], wm2 = g_wmul[b][2];
    float bd0 = g_badd[b][0], bd1 = g_badd[b][1], bd2 = g_badd[b][2];
    float acc = 0.f;
    for (int i = threadIdx.x; i < 6144; i += 256) {
        int idx = start + i;
        int c = idx % 3;
        float wm = c == 0 ? wm0 : (c == 1 ? wm1 : wm2);
        float bd = c == 0 ? bd0 : (c == 1 ? bd1 : bd2);
        float v = __fadd_rn(__fmul_rn(wm, patch[idx]), bd);
        v = fminf(fmaxf(v, -1.0f), 1.0f);
        acc += v;
    }
    sh[threadIdx.x] = acc; __syncthreads();
    for (int o = 128; o > 0; o >>= 1) {
        if (threadIdx.x < o) sh[threadIdx.x] += sh[threadIdx.x + o];
        __syncthreads();
    }
    if (threadIdx.x == 0) g_part_p1[blk] = sh[0];
}

// ---------------- K4: finalize means -> brightness offset ----------------
__global__ void k_finalize() {
    __shared__ float sh[128];
    int b = blockIdx.x, t = threadIdx.x;
    sh[t] = g_part_img[b*128 + t]; __syncthreads();
    for (int o = 64; o > 0; o >>= 1) { if (t < o) sh[t] += sh[t+o]; __syncthreads(); }
    float simg = sh[0]; __syncthreads();
    sh[t] = (t < 32) ? g_part_p1[b*32 + t] : 0.f; __syncthreads();
    for (int o = 64; o > 0; o >>= 1) { if (t < o) sh[t] += sh[t+o]; __syncthreads(); }
    if (t == 0) {
        float mi = __fdiv_rn(simg, 1228800.0f);
        float mp = __fdiv_rn(sh[0], 196608.0f);
        g_offset[b] = __fsub_rn(mi, mp);
    }
}

// ---------------- K5: materialize per-image adjusted patch ----------------
__global__ void k_build_patch(const float* __restrict__ patch) {
    int idx = blockIdx.x * blockDim.x + threadIdx.x;
    if (idx >= BB * PATCH_ELEMS) return;
    int b = idx / PATCH_ELEMS;
    int r = idx - b * PATCH_ELEMS;
    int c = r % 3;
    float v = __fadd_rn(__fmul_rn(g_wmul[b][c], patch[r]), g_badd[b][c]);
    v = fminf(fmaxf(v, -1.0f), 1.0f);
    v = __fadd_rn(v, g_offset[b]);
    v = fminf(fmaxf(v, -1.0f), 1.0f);
    g_patch[b][r] = v;
}

// ---------------- K6: main per-pixel pass (last box wins) ----------------
__global__ void __launch_bounds__(256) k_main(const float* __restrict__ images,
                                              float* __restrict__ out) {
    __shared__ BoxParam sbox[NBOX];
    int b = blockIdx.x / 1600;    // 1600 blocks per image
    {
        const unsigned* src = (const unsigned*)(&g_box[b][0]);
        unsigned* dst = (unsigned*)(&sbox[0]);
        const int nw = NBOX * (int)(sizeof(BoxParam) / 4);
        for (int i = threadIdx.x; i < nw; i += 256) dst[i] = src[i];
    }
    __syncthreads();
    int gid = blockIdx.x * 256 + threadIdx.x;
    int pix = gid - b * (HH * WW);
    int y = pix / WW;
    int x = pix - y * WW;
    float yf = (float)y, xf = (float)x;
    size_t off = (size_t)gid * 3;
    float r0 = images[off], r1 = images[off + 1], r2 = images[off + 2];
    const float* pb = g_patch[b];

#pragma unroll 1
    for (int j = NBOX - 1; j >= 0; --j) {
        const BoxParam bp = sbox[j];
        if (!bp.valid) continue;
        float u = __fsub_rn(yf, bp.y0f);
        float v = __fsub_rn(xf, bp.x0f);
        if (!(u >= 0.0f && u < bp.diagf && v >= 0.0f && v < bp.diagf)) continue;
        float vc = __fsub_rn(v, bp.cc);
        float uc = __fsub_rn(u, bp.cc);
        float sv = __fadd_rn(__fsub_rn(__fmul_rn(bp.ca, vc), __fmul_rn(bp.sa, uc)), bp.cc);
        float su = __fadd_rn(__fadd_rn(__fmul_rn(bp.sa, vc), __fmul_rn(bp.ca, uc)), bp.cc);
        float ry = __fsub_rn(su, bp.top);
        float rx = __fsub_rn(sv, bp.top);
        if (!(ry >= 0.0f && ry <= bp.phm1 && rx >= 0.0f && rx <= bp.phm1)) continue;

        float py = __fsub_rn(__fmul_rn(__fadd_rn(ry, 0.5f), bp.sfac), 0.5f);
        float px = __fsub_rn(__fmul_rn(__fadd_rn(rx, 0.5f), bp.sfac), 0.5f);
        float fy = floorf(py), fx = floorf(px);
        float wy = __fsub_rn(py, fy), wx = __fsub_rn(px, fx);
        int y0i = (int)fy; y0i = y0i < 0 ? 0 : (y0i > 255 ? 255 : y0i);
        int x0i = (int)fx; x0i = x0i < 0 ? 0 : (x0i > 255 ? 255 : x0i);
        int y1i = y0i + 1 > 255 ? 255 : y0i + 1;
        int x1i = x0i + 1 > 255 ? 255 : x0i + 1;
        int base00 = (y0i * 256 + x0i) * 3;
        int base01 = (y0i * 256 + x1i) * 3;
        int base10 = (y1i * 256 + x0i) * 3;
        int base11 = (y1i * 256 + x1i) * 3;
        float omwx = __fsub_rn(1.0f, wx), omwy = __fsub_rn(1.0f, wy);
        int mbase = (y * WW + x) * 3;
        float res[3];
#pragma unroll
        for (int c = 0; c < 3; c++) {
            float v00 = pb[base00 + c], v01 = pb[base01 + c];
            float v10 = pb[base10 + c], v11 = pb[base11 + c];
            float t0 = __fadd_rn(__fmul_rn(omwx, v00), __fmul_rn(wx, v01));
            float t1 = __fadd_rn(__fmul_rn(omwx, v10), __fmul_rn(wx, v11));
            float bil = __fadd_rn(__fmul_rn(omwy, t0), __fmul_rn(wy, t1));
            unsigned bits = rbits32(bp.kn0, bp.kn1, (unsigned)(mbase + c));
            float nz = fmaxf(-0.01f, __fadd_rn(__fmul_rn(u01f(bits), 0.02f), -0.01f));
            float val = __fadd_rn(__fadd_rn(bil, nz), bp.delta);
            res[c] = fminf(fmaxf(val, -1.0f), 1.0f);
        }
        r0 = res[0]; r1 = res[1]; r2 = res[2];
        break;   // highest j wins (scan applies boxes in order; later overwrite)
    }
    out[off] = r0; out[off + 1] = r1; out[off + 2] = r2;
}

extern "C" void kernel_launch(void* const* d_in, const int* in_sizes, int n_in,
                              void* d_out, int out_size) {
    const float *images = nullptr, *boxes = nullptr, *patch = nullptr, *scalep = nullptr;
    for (int i = 0; i < n_in; i++) {
        if      (in_sizes[i] == BB * IMG_ELEMS)  images = (const float*)d_in[i];
        else if (in_sizes[i] == BB * NBOX * 4)   boxes  = (const float*)d_in[i];
        else if (in_sizes[i] == PATCH_ELEMS)     patch  = (const float*)d_in[i];
        else if (in_sizes[i] == 1)               scalep = (const float*)d_in[i];
    }
    float* out = (float*)d_out;
    k_setup<<<1, 128>>>(boxes, scalep);
    k_img_partial<<<1024, 256>>>(images);
    k_p1_partial<<<256, 256>>>(patch);
    k_finalize<<<BB, 128>>>();
    k_build_patch<<<(BB * PATCH_ELEMS + 255) / 256, 256>>>(patch);
    k_main<<<BB * HH * WW / 256, 256>>>(images, out);
}